// round 3
// baseline (speedup 1.0000x reference)
#include <cuda_runtime.h>
#include <cuda_bf16.h>
#include <cstdint>

// LIF neuron forward scan over STEP=4 time steps.
// x:   [STEP, B, C, H, W] fp32  (default spatial = 64*128*32*32 = 8,388,608)
// out: [STEP, B, C, H, W] fp32, spike in {0,1}
//
// Per spatial position, t = 0..3:
//   mem = mem*0.25 + x_t;  spike = (mem > 0.5);  out_t = spike;  mem = spike ? 0 : mem
// (forward of the surrogate-gradient spike activation is the hard threshold)
//
// Pure HBM streaming: read 4 planes, write 4 planes. Vectorized float4 with
// 2 float4 per thread iteration (8 front-batched loads -> MLP=8), grid-stride,
// plus a scalar tail for non-multiple-of-4 spatial sizes.

#define LIF_DECAY 0.25f
#define LIF_STEP  4

__device__ __forceinline__ void lif_scan4(const float4 xt[LIF_STEP], float4 o[LIF_STEP])
{
    float4 mem = make_float4(0.f, 0.f, 0.f, 0.f);
#pragma unroll
    for (int t = 0; t < LIF_STEP; ++t) {
        mem.x = fmaf(mem.x, LIF_DECAY, xt[t].x);
        o[t].x = (mem.x > 0.5f) ? 1.0f : 0.0f;
        mem.x  = (mem.x > 0.5f) ? 0.0f : mem.x;

        mem.y = fmaf(mem.y, LIF_DECAY, xt[t].y);
        o[t].y = (mem.y > 0.5f) ? 1.0f : 0.0f;
        mem.y  = (mem.y > 0.5f) ? 0.0f : mem.y;

        mem.z = fmaf(mem.z, LIF_DECAY, xt[t].z);
        o[t].z = (mem.z > 0.5f) ? 1.0f : 0.0f;
        mem.z  = (mem.z > 0.5f) ? 0.0f : mem.z;

        mem.w = fmaf(mem.w, LIF_DECAY, xt[t].w);
        o[t].w = (mem.w > 0.5f) ? 1.0f : 0.0f;
        mem.w  = (mem.w > 0.5f) ? 0.0f : mem.w;
    }
}

__global__ __launch_bounds__(256)
void LIFAct_17051020165839_vec(const float4* __restrict__ x,
                               float4* __restrict__ out,
                               int n4)  // float4 count per time step
{
    const int stride = gridDim.x * blockDim.x;
    // Process 2 float4 per iteration for MLP=8 on the front-batched loads.
    for (int i = blockIdx.x * blockDim.x + threadIdx.x; i < n4; i += 2 * stride) {
        const int j = i + stride;
        const bool has_j = (j < n4);

        float4 xa[LIF_STEP], xb[LIF_STEP];
#pragma unroll
        for (int t = 0; t < LIF_STEP; ++t) {
            xa[t] = x[(size_t)t * n4 + i];
        }
        if (has_j) {
#pragma unroll
            for (int t = 0; t < LIF_STEP; ++t) {
                xb[t] = x[(size_t)t * n4 + j];
            }
        }

        float4 oa[LIF_STEP], ob[LIF_STEP];
        lif_scan4(xa, oa);
#pragma unroll
        for (int t = 0; t < LIF_STEP; ++t) {
            out[(size_t)t * n4 + i] = oa[t];
        }
        if (has_j) {
            lif_scan4(xb, ob);
#pragma unroll
            for (int t = 0; t < LIF_STEP; ++t) {
                out[(size_t)t * n4 + j] = ob[t];
            }
        }
    }
}

// Scalar tail for spatial sizes not divisible by 4.
__global__ __launch_bounds__(256)
void LIFAct_17051020165839_tail(const float* __restrict__ x,
                                float* __restrict__ out,
                                int per_step, int tail_start)
{
    const int i = tail_start + blockIdx.x * blockDim.x + threadIdx.x;
    if (i >= per_step) return;

    float mem = 0.0f;
#pragma unroll
    for (int t = 0; t < LIF_STEP; ++t) {
        mem = fmaf(mem, LIF_DECAY, x[(size_t)t * per_step + i]);
        const bool s = (mem > 0.5f);
        out[(size_t)t * per_step + i] = s ? 1.0f : 0.0f;
        mem = s ? 0.0f : mem;
    }
}

extern "C" void kernel_launch(void* const* d_in, const int* in_sizes, int n_in,
                              void* d_out, int out_size)
{
    const float* x = (const float*)d_in[0];
    float* out = (float*)d_out;

    const int total = in_sizes[0];           // STEP * spatial
    const int per_step = total / LIF_STEP;   // spatial element count
    const int n4 = per_step / 4;             // full float4 chunks per time step

    if (n4 > 0) {
        const int threads = 256;
        const int iters_per_thread = 2;
        int blocks = (n4 + threads * iters_per_thread - 1) / (threads * iters_per_thread);
        if (blocks < 1) blocks = 1;
        LIFAct_17051020165839_vec<<<blocks, threads>>>(
            (const float4*)x, (float4*)out, n4);
    }

    const int tail_start = n4 * 4;
    const int tail = per_step - tail_start;
    if (tail > 0) {
        const int threads = 256;
        const int blocks = (tail + threads - 1) / threads;
        LIFAct_17051020165839_tail<<<blocks, threads>>>(x, out, per_step, tail_start);
    }
}

// round 4
// speedup vs baseline: 1.0086x; 1.0086x over previous
#include <cuda_runtime.h>
#include <cuda_bf16.h>
#include <cstdint>

// LIF neuron forward scan over STEP=4 time steps.
// x:   [STEP, B, C, H, W] fp32  (default spatial = 64*128*32*32 = 8,388,608)
// out: [STEP, B, C, H, W] fp32, spike in {0,1}
//
// Per spatial position, t = 0..3:
//   mem = mem*0.25 + x_t;  spike = (mem > 0.5);  out_t = spike;  mem = spike ? 0 : mem
//
// Pure HBM streaming (read-once / write-once): all global accesses use
// evict-first streaming hints (__ldcs/__stcs) so L2 never retains dead lines.
// 2 float4 per thread -> 8 front-batched LDG.128 (MLP=8).

#define LIF_DECAY 0.25f
#define LIF_STEP  4

__device__ __forceinline__ void lif_scan4(const float4 xt[LIF_STEP], float4 o[LIF_STEP])
{
    float4 mem = make_float4(0.f, 0.f, 0.f, 0.f);
#pragma unroll
    for (int t = 0; t < LIF_STEP; ++t) {
        mem.x = fmaf(mem.x, LIF_DECAY, xt[t].x);
        o[t].x = (mem.x > 0.5f) ? 1.0f : 0.0f;
        mem.x  = (mem.x > 0.5f) ? 0.0f : mem.x;

        mem.y = fmaf(mem.y, LIF_DECAY, xt[t].y);
        o[t].y = (mem.y > 0.5f) ? 1.0f : 0.0f;
        mem.y  = (mem.y > 0.5f) ? 0.0f : mem.y;

        mem.z = fmaf(mem.z, LIF_DECAY, xt[t].z);
        o[t].z = (mem.z > 0.5f) ? 1.0f : 0.0f;
        mem.z  = (mem.z > 0.5f) ? 0.0f : mem.z;

        mem.w = fmaf(mem.w, LIF_DECAY, xt[t].w);
        o[t].w = (mem.w > 0.5f) ? 1.0f : 0.0f;
        mem.w  = (mem.w > 0.5f) ? 0.0f : mem.w;
    }
}

__global__ __launch_bounds__(512)
void LIFAct_17051020165839_vec(const float4* __restrict__ x,
                               float4* __restrict__ out,
                               int n4)  // float4 count per time step
{
    const int stride = gridDim.x * blockDim.x;
    const int i = blockIdx.x * blockDim.x + threadIdx.x;
    if (i >= n4) return;
    const int j = i + stride;
    const bool has_j = (j < n4);

    // Front-batch all loads (up to 8 independent LDG.128 -> MLP=8),
    // streaming (evict-first) since each line is read exactly once.
    float4 xa[LIF_STEP], xb[LIF_STEP];
#pragma unroll
    for (int t = 0; t < LIF_STEP; ++t) {
        xa[t] = __ldcs(&x[(size_t)t * n4 + i]);
    }
    if (has_j) {
#pragma unroll
        for (int t = 0; t < LIF_STEP; ++t) {
            xb[t] = __ldcs(&x[(size_t)t * n4 + j]);
        }
    }

    float4 oa[LIF_STEP], ob[LIF_STEP];
    lif_scan4(xa, oa);
#pragma unroll
    for (int t = 0; t < LIF_STEP; ++t) {
        __stcs(&out[(size_t)t * n4 + i], oa[t]);
    }
    if (has_j) {
        lif_scan4(xb, ob);
#pragma unroll
        for (int t = 0; t < LIF_STEP; ++t) {
            __stcs(&out[(size_t)t * n4 + j], ob[t]);
        }
    }
}

// Scalar tail for spatial sizes not divisible by 4 (not launched for the
// default shape).
__global__ __launch_bounds__(256)
void LIFAct_17051020165839_tail(const float* __restrict__ x,
                                float* __restrict__ out,
                                int per_step, int tail_start)
{
    const int i = tail_start + blockIdx.x * blockDim.x + threadIdx.x;
    if (i >= per_step) return;

    float mem = 0.0f;
#pragma unroll
    for (int t = 0; t < LIF_STEP; ++t) {
        mem = fmaf(mem, LIF_DECAY, __ldcs(&x[(size_t)t * per_step + i]));
        const bool s = (mem > 0.5f);
        __stcs(&out[(size_t)t * per_step + i], s ? 1.0f : 0.0f);
        mem = s ? 0.0f : mem;
    }
}

extern "C" void kernel_launch(void* const* d_in, const int* in_sizes, int n_in,
                              void* d_out, int out_size)
{
    const float* x = (const float*)d_in[0];
    float* out = (float*)d_out;

    const int total = in_sizes[0];           // STEP * spatial
    const int per_step = total / LIF_STEP;   // spatial element count
    const int n4 = per_step / 4;             // full float4 chunks per time step

    if (n4 > 0) {
        const int threads = 512;
        const int iters_per_thread = 2;
        int blocks = (n4 + threads * iters_per_thread - 1) / (threads * iters_per_thread);
        if (blocks < 1) blocks = 1;
        LIFAct_17051020165839_vec<<<blocks, threads>>>(
            (const float4*)x, (float4*)out, n4);
    }

    const int tail_start = n4 * 4;
    const int tail = per_step - tail_start;
    if (tail > 0) {
        const int threads = 256;
        const int blocks = (tail + threads - 1) / threads;
        LIFAct_17051020165839_tail<<<blocks, threads>>>(x, out, per_step, tail_start);
    }
}